// round 1
// baseline (speedup 1.0000x reference)
#include <cuda_runtime.h>
#include <math.h>

// Problem constants
#define B_  2
#define W_  4096
#define R_  8
#define D_  32
#define C_  64                 // chunk length
#define NC_ (W_ / C_)          // 64 chunks

// Scratch (device globals — no allocation allowed)
__device__ float g_L  [B_ * NC_ * R_ * D_];   // per-chunk local decayed sums
__device__ float g_Sin[B_ * NC_ * R_ * D_];   // state entering each chunk

// ---------------------------------------------------------------------------
// Kernel 1: per-chunk local sums  L_c[r,d] = sum_j gamma_r^{C-1-j} k[j,r] h[j,d]
// grid = B*NC blocks, 256 threads (one per (r,d))
// ---------------------------------------------------------------------------
__global__ void __launch_bounds__(256, 1)
k_localsum(const float* __restrict__ kin, const float* __restrict__ hin,
           const float* __restrict__ gamma)
{
    const int blk = blockIdx.x;
    const int b = blk / NC_, c = blk % NC_;
    const int w0 = c * C_;

    __shared__ float kT[R_][C_];       // transposed k chunk
    __shared__ float hs[C_][D_];

    const int t = threadIdx.x;

    // load k chunk [C_,R_] (512 floats), transpose into kT
    for (int idx = t; idx < C_ * R_; idx += 256) {
        int j = idx / R_, r = idx % R_;
        kT[r][j] = kin[(b * W_ + w0 + j) * R_ + r];
    }
    // load h chunk [C_,D_] (2048 floats), contiguous
    for (int idx = t; idx < C_ * D_; idx += 256) {
        ((float*)hs)[idx] = hin[(b * W_ + w0) * D_ + idx];
    }
    __syncthreads();

    const int r = t / D_;              // 0..7
    const int d = t % D_;              // 0..31
    const float g = __ldg(&gamma[r]);

    // Horner: acc = sum_j g^{C-1-j} * k[j]*h[j]
    float acc = 0.f;
#pragma unroll
    for (int j = 0; j < C_; ++j) {
        acc = fmaf(g, acc, kT[r][j] * hs[j][d]);
    }
    g_L[((b * NC_ + c) * R_ + r) * D_ + d] = acc;
}

// ---------------------------------------------------------------------------
// Kernel 2: sequential scan over chunks.
// 1 block, 512 threads (one per (b,r,d)).
//   Sin[c] = S_{c-1};  S_c = g^C * S_{c-1} + L_c   (S_{-1} = 0)
// ---------------------------------------------------------------------------
__global__ void __launch_bounds__(512, 1)
k_scan(const float* __restrict__ gamma)
{
    const int t  = threadIdx.x;        // 0..511
    const int b  = t >> 8;             // 0..1
    const int rd = t & 255;            // 0..255
    const int r  = rd >> 5;

    const float g = __ldg(&gamma[r]);
    // g^64 by repeated squaring
    float g2  = g  * g;
    float g4  = g2 * g2;
    float g8  = g4 * g4;
    float g16 = g8 * g8;
    float g32 = g16 * g16;
    float gC  = g32 * g32;

    float s = 0.f;
#pragma unroll 4
    for (int c = 0; c < NC_; ++c) {
        const int base = (b * NC_ + c) * (R_ * D_) + rd;
        g_Sin[base] = s;
        s = fmaf(gC, s, g_L[base]);
    }
}

// ---------------------------------------------------------------------------
// Kernel 3: per-chunk output.
//   A[i][j] = sum_r q[i,r] k[j,r] g_r^{i-j}   (j<=i)
//   out[i,d] = sum_{j<=i} A[i][j] h[j][d] + sum_r q[i,r] g_r^{i+1} Sin[r][d]
// grid = B*NC blocks, 256 threads
// ---------------------------------------------------------------------------
__global__ void __launch_bounds__(256, 1)
k_output(const float* __restrict__ qin, const float* __restrict__ kin,
         const float* __restrict__ hin, const float* __restrict__ gamma,
         float* __restrict__ out)
{
    const int blk = blockIdx.x;
    const int b = blk / NC_, c = blk % NC_;
    const int w0 = c * C_;

    __shared__ float qs [C_][R_];
    __shared__ float kT [R_][C_];
    __shared__ float hs [C_][D_];
    __shared__ float pw [R_][C_ + 1];     // gamma_r^t, t = 0..C
    __shared__ float A  [C_][C_];
    __shared__ float Sin[R_][D_];

    const int t = threadIdx.x;

    for (int idx = t; idx < C_ * R_; idx += 256) {
        int j = idx / R_, r = idx % R_;
        float kv = kin[(b * W_ + w0 + j) * R_ + r];
        float qv = qin[(b * W_ + w0 + j) * R_ + r];
        kT[r][j] = kv;
        qs[j][r] = qv;
    }
    for (int idx = t; idx < C_ * D_; idx += 256) {
        ((float*)hs)[idx] = hin[(b * W_ + w0) * D_ + idx];
    }
    for (int idx = t; idx < R_ * D_; idx += 256) {
        ((float*)Sin)[idx] = g_Sin[(b * NC_ + c) * (R_ * D_) + idx];
    }
    // power table: 8 * 65 = 520 entries
    for (int idx = t; idx < R_ * (C_ + 1); idx += 256) {
        int r = idx / (C_ + 1), tt = idx % (C_ + 1);
        float lg = __log2f(__ldg(&gamma[r]));
        pw[r][tt] = exp2f((float)tt * lg);
    }
    __syncthreads();

    // Stage 1: A matrix (lower triangle; upper left as-is but never read)
    for (int idx = t; idx < C_ * C_; idx += 256) {
        int i = idx / C_, j = idx % C_;
        if (j <= i) {
            const int dt = i - j;
            float a = 0.f;
#pragma unroll
            for (int r = 0; r < R_; ++r)
                a = fmaf(qs[i][r] * pw[r][dt], kT[r][j], a);
            A[i][j] = a;
        }
    }
    __syncthreads();

    // Stage 2: outputs. warp w handles rows i = w*8 .. w*8+7, lane = d.
    const int warp = t >> 5;
    const int d    = t & 31;
#pragma unroll
    for (int ii = 0; ii < 8; ++ii) {
        const int i = warp * 8 + ii;

        // inter-chunk contribution: sum_r q[i,r] * g_r^{i+1} * Sin[r,d]
        float acc = 0.f;
#pragma unroll
        for (int r = 0; r < R_; ++r)
            acc = fmaf(qs[i][r] * pw[r][i + 1], Sin[r][d], acc);

        // intra-chunk: A row broadcast across lanes, hs conflict-free by lane=d
        for (int j = 0; j <= i; ++j)
            acc = fmaf(A[i][j], hs[j][d], acc);

        out[(b * W_ + w0 + i) * D_ + d] = acc;
    }
}

// ---------------------------------------------------------------------------
// Launch: inputs per metadata order:
//   0: q_alpha [B,W,R]  1: k [B,W,R]  2: h_norm [B,W,D]
//   3: gamma_vec [R]    4: causal_mask [W,W] (unused)  5: decay_diff (unused)
// out: float32 [B,W,D]
// ---------------------------------------------------------------------------
extern "C" void kernel_launch(void* const* d_in, const int* in_sizes, int n_in,
                              void* d_out, int out_size)
{
    const float* q     = (const float*)d_in[0];
    const float* k     = (const float*)d_in[1];
    const float* h     = (const float*)d_in[2];
    const float* gamma = (const float*)d_in[3];
    float* out         = (float*)d_out;

    k_localsum<<<B_ * NC_, 256>>>(k, h, gamma);
    k_scan<<<1, 512>>>(gamma);
    k_output<<<B_ * NC_, 256>>>(q, k, h, gamma, out);
}

// round 3
// speedup vs baseline: 1.5059x; 1.5059x over previous
#include <cuda_runtime.h>
#include <math.h>

// Problem constants
#define B_  2
#define W_  4096
#define R_  8
#define D_  32
#define C_  64                 // chunk length
#define NC_ (W_ / C_)          // 64 chunks

// Scratch (device global — no allocation allowed)
__device__ float g_L[B_ * NC_ * R_ * D_];   // per-chunk local decayed sums

// ---------------------------------------------------------------------------
// Kernel 1: per-chunk local sums  L_c[r,d] = sum_j gamma_r^{C-1-j} k[j,r] h[j,d]
// grid = B*NC = 128 blocks, 256 threads (one per (r,d)); float4 loads.
// ---------------------------------------------------------------------------
__global__ void __launch_bounds__(256, 1)
k_localsum(const float* __restrict__ kin, const float* __restrict__ hin,
           const float* __restrict__ gamma)
{
    const int blk = blockIdx.x;
    const int b = blk / NC_, c = blk % NC_;
    const int w0 = c * C_;

    __shared__ float kT[R_][C_];       // transposed k chunk
    __shared__ float hs[C_][D_];

    const int t = threadIdx.x;

    // h chunk: 2048 floats = 512 float4, 2 per thread, contiguous
    {
        const float4* h4 = (const float4*)(hin + (size_t)(b * W_ + w0) * D_);
        float4* hs4 = (float4*)hs;
        hs4[t]       = h4[t];
        hs4[t + 256] = h4[t + 256];
    }
    // k chunk: 512 floats = 128 float4, threads 0..127, transpose into kT
    if (t < 128) {
        const float4* k4 = (const float4*)(kin + (size_t)(b * W_ + w0) * R_);
        float4 v = k4[t];
        int j  = t >> 1;
        int r0 = (t & 1) * 4;
        kT[r0 + 0][j] = v.x;
        kT[r0 + 1][j] = v.y;
        kT[r0 + 2][j] = v.z;
        kT[r0 + 3][j] = v.w;
    }
    __syncthreads();

    const int r = t >> 5;              // 0..7
    const int d = t & 31;              // 0..31
    const float g  = __ldg(&gamma[r]);
    const float g2 = g * g;

    // Split Horner: acc = g*E + O, two 32-length chains with ratio g^2
    float E = 0.f, O = 0.f;
#pragma unroll
    for (int m = 0; m < 32; ++m) {
        E = fmaf(g2, E, kT[r][2 * m]     * hs[2 * m][d]);
        O = fmaf(g2, O, kT[r][2 * m + 1] * hs[2 * m + 1][d]);
    }
    g_L[((b * NC_ + c) * R_ + r) * D_ + d] = fmaf(g, E, O);
}

// ---------------------------------------------------------------------------
// Kernel 2: per-chunk output, with the chunk-entry state Sin computed inline.
//   Sin[r,d]  = sum_{c'<c} (gamma_r^C)^{c-1-c'} L[c'][r][d]
//   A[i][j]   = sum_r q[i,r] k[j,r] gamma_r^{i-j}   (j<=i; 0 above diagonal)
//   out[i,d]  = sum_j A[i][j] hs[j][d] + sum_r q[i,r] gamma_r^{i+1} Sin[r][d]
// grid = B*NC = 128 blocks, 256 threads
// ---------------------------------------------------------------------------
__global__ void __launch_bounds__(256, 1)
k_output(const float* __restrict__ qin, const float* __restrict__ kin,
         const float* __restrict__ hin, const float* __restrict__ gamma,
         float* __restrict__ out)
{
    const int blk = blockIdx.x;
    const int b = blk / NC_, c = blk % NC_;
    const int w0 = c * C_;

    __shared__ float qs [C_][R_];
    __shared__ float kT [R_][C_];
    __shared__ float hs [C_][D_];
    __shared__ float pw [R_][C_ + 1];     // gamma_r^t, t = 0..C
    __shared__ float A  [C_][C_];
    __shared__ float Sin[R_][D_];

    const int t = threadIdx.x;

    // ---- loads (float4) ----
    {
        const float4* h4 = (const float4*)(hin + (size_t)(b * W_ + w0) * D_);
        float4* hs4 = (float4*)hs;
        hs4[t]       = h4[t];
        hs4[t + 256] = h4[t + 256];
    }
    if (t < 128) {
        const float4* k4 = (const float4*)(kin + (size_t)(b * W_ + w0) * R_);
        float4 v = k4[t];
        int j = t >> 1, r0 = (t & 1) * 4;
        kT[r0 + 0][j] = v.x; kT[r0 + 1][j] = v.y;
        kT[r0 + 2][j] = v.z; kT[r0 + 3][j] = v.w;
    } else {
        const float4* q4 = (const float4*)(qin + (size_t)(b * W_ + w0) * R_);
        int tt = t - 128;
        float4 v = q4[tt];
        int j = tt >> 1, r0 = (tt & 1) * 4;
        qs[j][r0 + 0] = v.x; qs[j][r0 + 1] = v.y;
        qs[j][r0 + 2] = v.z; qs[j][r0 + 3] = v.w;
    }

    // ---- power table: gamma_r^tt, 8*65 entries ----
    for (int idx = t; idx < R_ * (C_ + 1); idx += 256) {
        int r = idx / (C_ + 1), tt = idx % (C_ + 1);
        float lg = __log2f(__ldg(&gamma[r]));
        pw[r][tt] = exp2f((float)tt * lg);
    }

    // ---- inline Sin: thread (r,d) Horner over previous chunks ----
    {
        const int r = t >> 5;
        const int d = t & 31;
        const float g  = __ldg(&gamma[r]);
        float g2  = g * g;
        float g4  = g2 * g2;
        float g8  = g4 * g4;
        float g16 = g8 * g8;
        float g32 = g16 * g16;
        float gC  = g32 * g32;          // gamma^64

        const float* Lp = &g_L[(size_t)b * NC_ * R_ * D_ + (size_t)r * D_ + d];
        float s = 0.f;
#pragma unroll 4
        for (int cp = 0; cp < c; ++cp) {
            s = fmaf(gC, s, Lp[(size_t)cp * (R_ * D_)]);
        }
        Sin[r][d] = s;
    }
    __syncthreads();

    // ---- Stage 1: A matrix (zero-filled above diagonal) ----
    for (int idx = t; idx < C_ * C_; idx += 256) {
        int i = idx >> 6, j = idx & 63;
        float a = 0.f;
        if (j <= i) {
            const int dt = i - j;
#pragma unroll
            for (int r = 0; r < R_; ++r)
                a = fmaf(qs[i][r] * pw[r][dt], kT[r][j], a);
        }
        A[i][j] = a;
    }
    __syncthreads();

    // ---- Stage 2: outputs. warp w -> rows 8w..8w+7, lane -> d ----
    const int warp = t >> 5;
    const int d    = t & 31;
#pragma unroll
    for (int ii = 0; ii < 8; ++ii) {
        const int i = warp * 8 + ii;

        // inter-chunk contribution
        float acc = 0.f;
#pragma unroll
        for (int r = 0; r < R_; ++r)
            acc = fmaf(qs[i][r] * pw[r][i + 1], Sin[r][d], acc);

        // intra-chunk: unroll-by-4; A zero above diagonal so over-read is safe
        for (int j = 0; j <= i; j += 4) {
            acc = fmaf(A[i][j],     hs[j][d],     acc);
            acc = fmaf(A[i][j + 1], hs[j + 1][d], acc);
            acc = fmaf(A[i][j + 2], hs[j + 2][d], acc);
            acc = fmaf(A[i][j + 3], hs[j + 3][d], acc);
        }

        out[(size_t)(b * W_ + w0 + i) * D_ + d] = acc;
    }
}

// ---------------------------------------------------------------------------
// Launch. Inputs (metadata order):
//   0: q_alpha [B,W,R]  1: k [B,W,R]  2: h_norm [B,W,D]
//   3: gamma_vec [R]    4: causal_mask (unused)  5: decay_diff (unused)
// out: float32 [B,W,D]
// ---------------------------------------------------------------------------
extern "C" void kernel_launch(void* const* d_in, const int* in_sizes, int n_in,
                              void* d_out, int out_size)
{
    const float* q     = (const float*)d_in[0];
    const float* k     = (const float*)d_in[1];
    const float* h     = (const float*)d_in[2];
    const float* gamma = (const float*)d_in[3];
    float* out         = (float*)d_out;

    k_localsum<<<B_ * NC_, 256>>>(k, h, gamma);
    k_output<<<B_ * NC_, 256>>>(q, k, h, gamma, out);
}

// round 5
// speedup vs baseline: 2.4951x; 1.6569x over previous
#include <cuda_runtime.h>
#include <math.h>

// Problem constants
#define B_  2
#define W_  4096
#define R_  8
#define D_  32
#define C_  64                 // chunk length
#define NC_ (W_ / C_)          // 64 chunks
#define GRID_ (B_ * NC_)       // 128 blocks (<= 148 SMs: all co-resident)

// Scratch + barrier state (device globals — no allocation allowed)
__device__ float g_L[B_ * NC_ * R_ * D_];   // per-chunk local decayed sums
__device__ int   g_bar  = 0;                // grid barrier arrivals
__device__ int   g_done = 0;                // completion counter (for reset)

// ---------------------------------------------------------------------------
// Fused kernel. One block per (b, chunk). 512 threads.
//  Phase A: L_c[r,d] = gamma^63 * sum_j kg[r][j] * h[j][d]   (kg = k*gamma^-j)
//  [grid barrier; A-matrix computed between arrive and spin]
//  Phase B: Sin[r,d] = Horner_{c'<c}(gamma^64, L[c'])
//           A[i][j]  = sum_r qg[i][r] * kg[r][j]   (j<=i, else 0)
//           out[i,d] = sum_j A[i][j] h[j][d] + sum_r qg[i][r]*gamma_r*Sin[r][d]
// ---------------------------------------------------------------------------
__global__ void __launch_bounds__(512, 1)
k_fused(const float* __restrict__ qin, const float* __restrict__ kin,
        const float* __restrict__ hin, const float* __restrict__ gamma,
        float* __restrict__ out)
{
    const int blk = blockIdx.x;
    const int b = blk / NC_, c = blk % NC_;
    const int w0 = c * C_;
    const int t = threadIdx.x;

    __shared__ float hs  [C_][D_];        // h chunk
    __shared__ float kgT [R_][C_];        // k * gamma^{-j}, transposed
    __shared__ float qg  [C_][R_];        // q * gamma^{i}
    __shared__ float A   [C_][C_ + 4];    // padded to kill store conflicts
    __shared__ float Sin [R_][D_];
    __shared__ float Pbuf[R_][D_];
    __shared__ float gam_s[R_];

    // ---- loads (float4) + decay pre-scaling ----
    {
        const float4* h4 = (const float4*)(hin + (size_t)(b * W_ + w0) * D_);
        ((float4*)hs)[t] = h4[t];         // 512 float4 = full 64x32 tile
    }
    if (t < 8) gam_s[t] = gamma[t];
    if (t < 128) {                        // k: 128 float4, transpose + gamma^-j
        const float4* k4 = (const float4*)(kin + (size_t)(b * W_ + w0) * R_);
        float4 v = k4[t];
        int j = t >> 1, r0 = (t & 1) * 4;
        float fj = -(float)j;
        kgT[r0 + 0][j] = v.x * exp2f(fj * __log2f(__ldg(&gamma[r0 + 0])));
        kgT[r0 + 1][j] = v.y * exp2f(fj * __log2f(__ldg(&gamma[r0 + 1])));
        kgT[r0 + 2][j] = v.z * exp2f(fj * __log2f(__ldg(&gamma[r0 + 2])));
        kgT[r0 + 3][j] = v.w * exp2f(fj * __log2f(__ldg(&gamma[r0 + 3])));
    } else if (t < 256) {                 // q: 128 float4, gamma^+i
        const float4* q4 = (const float4*)(qin + (size_t)(b * W_ + w0) * R_);
        int tt = t - 128;
        float4 v = q4[tt];
        int j = tt >> 1, r0 = (tt & 1) * 4;
        float fj = (float)j;
        qg[j][r0 + 0] = v.x * exp2f(fj * __log2f(__ldg(&gamma[r0 + 0])));
        qg[j][r0 + 1] = v.y * exp2f(fj * __log2f(__ldg(&gamma[r0 + 1])));
        qg[j][r0 + 2] = v.z * exp2f(fj * __log2f(__ldg(&gamma[r0 + 2])));
        qg[j][r0 + 3] = v.w * exp2f(fj * __log2f(__ldg(&gamma[r0 + 3])));
    }
    __syncthreads();

    // ---- Phase A: local decayed sums (512 threads: (half, r, d)) ----
    {
        const int d = t & 31, r = (t >> 5) & 7, half = t >> 8;
        const int j0 = half << 5;
        float a0 = 0.f, a1 = 0.f;
#pragma unroll
        for (int m = 0; m < 16; ++m) {
            a0 = fmaf(kgT[r][j0 + 2 * m],     hs[j0 + 2 * m][d],     a0);
            a1 = fmaf(kgT[r][j0 + 2 * m + 1], hs[j0 + 2 * m + 1][d], a1);
        }
        float part = a0 + a1;
        if (half == 0) Pbuf[r][d] = part;
        __syncthreads();
        if (half == 1) {
            float g63 = exp2f(63.f * __log2f(gam_s[r]));
            g_L[((b * NC_ + c) * R_ + r) * D_ + d] = g63 * (part + Pbuf[r][d]);
        }
    }
    __syncthreads();

    // ---- barrier arrive (release g_L) ----
    if (t == 0) {
        __threadfence();
        atomicAdd(&g_bar, 1);
    }

    // ---- Stage 1: A matrix (independent of g_L — overlaps other blocks) ----
    {
        const int i1 = t >> 3;            // 0..63
        const int jb = t & 7;             // 0..7
        float qr[8];
#pragma unroll
        for (int r = 0; r < 8; ++r) qr[r] = qg[i1][r];
#pragma unroll
        for (int jj = 0; jj < 8; ++jj) {
            const int j = jb + jj * 8;    // lanes hit consecutive j: no conflicts
            float a = 0.f;
#pragma unroll
            for (int r = 0; r < 8; ++r) a = fmaf(qr[r], kgT[r][j], a);
            A[i1][j] = (j <= i1) ? a : 0.f;
        }
    }
    __syncthreads();

    // ---- barrier spin (then acquire) ----
    if (t == 0) {
        while (atomicAdd(&g_bar, 0) < GRID_) { }
    }
    __syncthreads();
    __threadfence();

    // ---- Sin: Horner over previous chunks (threads 0..255, L2-direct loads) ----
    if (t < 256) {
        const int r = t >> 5, d = t & 31;
        const float gC = exp2f(64.f * __log2f(gam_s[r]));
        const float* Lp = g_L + (size_t)b * NC_ * R_ * D_ + r * D_ + d;
        float s = 0.f;
#pragma unroll 8
        for (int cp = 0; cp < c; ++cp)
            s = fmaf(gC, s, __ldcg(Lp + (size_t)cp * (R_ * D_)));
        Sin[r][d] = s;
    }
    __syncthreads();

    // ---- Stage 2: 16 warps, 4 balanced rows each ----
    {
        const int w = t >> 5;             // 0..15
        const int d = t & 31;
        const int r0 = w, r1 = 31 - w, r2 = 32 + w, r3 = 63 - w;

        float acc0 = 0.f, acc1 = 0.f, acc2 = 0.f, acc3 = 0.f;
        const int rmax = 63 - w;          // longest of the 4 rows
#pragma unroll 4
        for (int j = 0; j <= rmax; ++j) { // A==0 above diagonal: over-run safe
            const float hv = hs[j][d];
            acc0 = fmaf(A[r0][j], hv, acc0);
            acc1 = fmaf(A[r1][j], hv, acc1);
            acc2 = fmaf(A[r2][j], hv, acc2);
            acc3 = fmaf(A[r3][j], hv, acc3);
        }

        // inter-chunk term: sum_r qg[i][r] * gamma_r * Sin[r][d]
#pragma unroll
        for (int r = 0; r < 8; ++r) {
            const float gs = gam_s[r];
            const float sv = Sin[r][d];
            acc0 = fmaf(qg[r0][r] * gs, sv, acc0);
            acc1 = fmaf(qg[r1][r] * gs, sv, acc1);
            acc2 = fmaf(qg[r2][r] * gs, sv, acc2);
            acc3 = fmaf(qg[r3][r] * gs, sv, acc3);
        }

        float* ob = out + (size_t)(b * W_ + w0) * D_ + d;
        ob[(size_t)r0 * D_] = acc0;
        ob[(size_t)r1 * D_] = acc1;
        ob[(size_t)r2 * D_] = acc2;
        ob[(size_t)r3 * D_] = acc3;
    }

    // ---- reset barrier state for next graph replay ----
    __syncthreads();
    if (t == 0) {
        int v = atomicAdd(&g_done, 1);
        if (v == GRID_ - 1) {
            atomicExch(&g_bar, 0);
            atomicExch(&g_done, 0);
        }
    }
}

// ---------------------------------------------------------------------------
// Launch. Inputs (metadata order):
//   0: q_alpha [B,W,R]  1: k [B,W,R]  2: h_norm [B,W,D]
//   3: gamma_vec [R]    4: causal_mask (unused)  5: decay_diff (unused)
// out: float32 [B,W,D]
// ---------------------------------------------------------------------------
extern "C" void kernel_launch(void* const* d_in, const int* in_sizes, int n_in,
                              void* d_out, int out_size)
{
    const float* q     = (const float*)d_in[0];
    const float* k     = (const float*)d_in[1];
    const float* h     = (const float*)d_in[2];
    const float* gamma = (const float*)d_in[3];
    float* out         = (float*)d_out;

    k_fused<<<GRID_, 512>>>(q, k, h, gamma, out);
}

// round 8
// speedup vs baseline: 2.6305x; 1.0543x over previous
#include <cuda_runtime.h>
#include <math.h>

// Problem constants
#define B_  2
#define W_  4096
#define R_  8
#define D_  32
#define C_  64                 // chunk length
#define NC_ (W_ / C_)          // 64 chunks
#define GRID_ (B_ * NC_)       // 128 blocks (<= 148 SMs: all co-resident)

// Scratch + barrier state (device globals — no allocation allowed)
__device__ float g_L[B_ * NC_ * R_ * D_];   // per-chunk local decayed sums
__device__ unsigned g_bar  = 0;             // grid barrier arrivals
__device__ unsigned g_done = 0;             // completion counter (for reset)

// ---------------------------------------------------------------------------
// Fused kernel. One block per (b, chunk). 512 threads.
//  Phase A: L_c[r,d] = gamma^63 * sum_j kg[r][j] * h[j][d]   (kg = k*gamma^-j)
//  [grid barrier: fence-release + atomic arrive; ACQUIRE-LOAD polling;
//   A-matrix computed between arrive and poll to overlap other blocks]
//  Phase B: Sin[r,d] = Horner_{c'<c}(gamma^64, L[c'])
//           A[i][j]  = sum_r qg[i][r] * kg[r][j]   (j<=i, else 0)
//           out[i,d] = sum_j A[i][j] h[j][d] + sum_r qg[i][r]*gamma_r*Sin[r][d]
// ---------------------------------------------------------------------------
__global__ void __launch_bounds__(512, 1)
k_fused(const float* __restrict__ qin, const float* __restrict__ kin,
        const float* __restrict__ hin, const float* __restrict__ gamma,
        float* __restrict__ out)
{
    const int blk = blockIdx.x;
    const int b = blk / NC_, c = blk % NC_;
    const int w0 = c * C_;
    const int t = threadIdx.x;

    __shared__ float hs  [C_][D_];        // h chunk
    __shared__ float kgT [R_][C_];        // k * gamma^{-j}, transposed
    __shared__ float qg  [C_][R_];        // q * gamma^{i}
    __shared__ float A   [C_][C_ + 4];    // 68-float rows: 16B-aligned, pad vs conflicts
    __shared__ float Sin [R_][D_];
    __shared__ float Pbuf[R_][D_];
    __shared__ float gam_s[R_];

    // ---- loads (float4) + decay pre-scaling ----
    {
        const float4* h4 = (const float4*)(hin + (size_t)(b * W_ + w0) * D_);
        ((float4*)hs)[t] = h4[t];         // 512 float4 = full 64x32 tile
    }
    if (t < 8) gam_s[t] = gamma[t];
    if (t < 128) {                        // k: 128 float4, transpose + gamma^-j
        const float4* k4 = (const float4*)(kin + (size_t)(b * W_ + w0) * R_);
        float4 v = k4[t];
        int j = t >> 1, r0 = (t & 1) * 4;
        float fj = -(float)j;
        kgT[r0 + 0][j] = v.x * exp2f(fj * __log2f(__ldg(&gamma[r0 + 0])));
        kgT[r0 + 1][j] = v.y * exp2f(fj * __log2f(__ldg(&gamma[r0 + 1])));
        kgT[r0 + 2][j] = v.z * exp2f(fj * __log2f(__ldg(&gamma[r0 + 2])));
        kgT[r0 + 3][j] = v.w * exp2f(fj * __log2f(__ldg(&gamma[r0 + 3])));
    } else if (t < 256) {                 // q: 128 float4, gamma^+i
        const float4* q4 = (const float4*)(qin + (size_t)(b * W_ + w0) * R_);
        int tt = t - 128;
        float4 v = q4[tt];
        int j = tt >> 1, r0 = (tt & 1) * 4;
        float fj = (float)j;
        qg[j][r0 + 0] = v.x * exp2f(fj * __log2f(__ldg(&gamma[r0 + 0])));
        qg[j][r0 + 1] = v.y * exp2f(fj * __log2f(__ldg(&gamma[r0 + 1])));
        qg[j][r0 + 2] = v.z * exp2f(fj * __log2f(__ldg(&gamma[r0 + 2])));
        qg[j][r0 + 3] = v.w * exp2f(fj * __log2f(__ldg(&gamma[r0 + 3])));
    }
    __syncthreads();

    // ---- Phase A: local decayed sums (512 threads: (half, r, d)) ----
    {
        const int d = t & 31, r = (t >> 5) & 7, half = t >> 8;
        const int j0 = half << 5;
        float a0 = 0.f, a1 = 0.f;
#pragma unroll
        for (int m = 0; m < 16; ++m) {
            a0 = fmaf(kgT[r][j0 + 2 * m],     hs[j0 + 2 * m][d],     a0);
            a1 = fmaf(kgT[r][j0 + 2 * m + 1], hs[j0 + 2 * m + 1][d], a1);
        }
        float part = a0 + a1;
        if (half == 0) Pbuf[r][d] = part;
        __syncthreads();
        if (half == 1) {
            float g63 = exp2f(63.f * __log2f(gam_s[r]));
            g_L[((b * NC_ + c) * R_ + r) * D_ + d] = g63 * (part + Pbuf[r][d]);
        }
    }
    __syncthreads();

    // ---- barrier arrive: fence-release then relaxed atomic (t0 only).
    // hb chain: writers' stores -> bar.sync -> t0 fence.gpu -> atom  (PTX model)
    if (t == 0) {
        __threadfence();
        atomicAdd(&g_bar, 1u);
    }

    // ---- Stage 1: A matrix (independent of g_L — overlaps other blocks) ----
    {
        const int i1 = t >> 3;            // 0..63
        const int jb = t & 7;             // 0..7
        float qr[8];
#pragma unroll
        for (int r = 0; r < 8; ++r) qr[r] = qg[i1][r];
#pragma unroll
        for (int jj = 0; jj < 8; ++jj) {
            const int j = jb + jj * 8;    // lanes hit consecutive j: no conflicts
            float a = 0.f;
#pragma unroll
            for (int r = 0; r < 8; ++r) a = fmaf(qr[r], kgT[r][j], a);
            A[i1][j] = (j <= i1) ? a : 0.f;
        }
    }
    __syncthreads();

    // ---- barrier wait: ACQUIRE-LOAD polling (no atomic RMW contention) ----
    if (t == 0 && c > 0) {
        unsigned v;
        do {
            asm volatile("ld.acquire.gpu.global.u32 %0, [%1];"
                         : "=r"(v) : "l"(&g_bar) : "memory");
        } while (v < (unsigned)GRID_);
    }
    __syncthreads();

    // ---- Sin: pairwise Horner over previous chunks (threads 0..255) ----
    if (t < 256) {
        const int r = t >> 5, d = t & 31;
        const float gC  = exp2f(64.f * __log2f(gam_s[r]));
        const float gC2 = gC * gC;
        const float* Lp = g_L + (size_t)b * NC_ * R_ * D_ + r * D_ + d;
        float s = 0.f;
        int cp = 0;
        if (c & 1) { s = __ldcg(Lp); cp = 1; }
#pragma unroll 4
        for (; cp < c; cp += 2) {
            float e = fmaf(gC, __ldcg(Lp + (size_t)cp * (R_ * D_)),
                               __ldcg(Lp + (size_t)(cp + 1) * (R_ * D_)));
            s = fmaf(gC2, s, e);
        }
        Sin[r][d] = s;
    }
    __syncthreads();

    // ---- Stage 2: 16 warps; pair-split balanced rows, float4 A broadcasts ----
    {
        const int w = t >> 5;             // 0..15
        const int d = t & 31;
        const int r0 = w, r1 = 31 - w;    // lengths <= 32  -> j in [0,32)
        const int r2 = 32 + w, r3 = 63 - w; // lengths <= 64 -> j in [0,64)

        float acc0 = 0.f, acc1 = 0.f, acc2 = 0.f, acc3 = 0.f;

#pragma unroll
        for (int j4 = 0; j4 < 32; j4 += 4) {   // pair 1
            const float4 a0 = *(const float4*)&A[r0][j4];
            const float4 a1 = *(const float4*)&A[r1][j4];
            const float h0 = hs[j4 + 0][d], h1 = hs[j4 + 1][d];
            const float h2 = hs[j4 + 2][d], h3 = hs[j4 + 3][d];
            acc0 = fmaf(a0.x, h0, acc0); acc0 = fmaf(a0.y, h1, acc0);
            acc0 = fmaf(a0.z, h2, acc0); acc0 = fmaf(a0.w, h3, acc0);
            acc1 = fmaf(a1.x, h0, acc1); acc1 = fmaf(a1.y, h1, acc1);
            acc1 = fmaf(a1.z, h2, acc1); acc1 = fmaf(a1.w, h3, acc1);
        }
#pragma unroll
        for (int j4 = 0; j4 < 64; j4 += 4) {   // pair 2
            const float4 a2 = *(const float4*)&A[r2][j4];
            const float4 a3 = *(const float4*)&A[r3][j4];
            const float h0 = hs[j4 + 0][d], h1 = hs[j4 + 1][d];
            const float h2 = hs[j4 + 2][d], h3 = hs[j4 + 3][d];
            acc2 = fmaf(a2.x, h0, acc2); acc2 = fmaf(a2.y, h1, acc2);
            acc2 = fmaf(a2.z, h2, acc2); acc2 = fmaf(a2.w, h3, acc2);
            acc3 = fmaf(a3.x, h0, acc3); acc3 = fmaf(a3.y, h1, acc3);
            acc3 = fmaf(a3.z, h2, acc3); acc3 = fmaf(a3.w, h3, acc3);
        }

        // inter-chunk term: sum_r qg[i][r] * gamma_r * Sin[r][d]
#pragma unroll
        for (int r = 0; r < 8; ++r) {
            const float gs = gam_s[r];
            const float sv = Sin[r][d];
            acc0 = fmaf(qg[r0][r] * gs, sv, acc0);
            acc1 = fmaf(qg[r1][r] * gs, sv, acc1);
            acc2 = fmaf(qg[r2][r] * gs, sv, acc2);
            acc3 = fmaf(qg[r3][r] * gs, sv, acc3);
        }

        float* ob = out + (size_t)(b * W_ + w0) * D_ + d;
        ob[(size_t)r0 * D_] = acc0;
        ob[(size_t)r1 * D_] = acc1;
        ob[(size_t)r2 * D_] = acc2;
        ob[(size_t)r3 * D_] = acc3;
    }

    // ---- reset barrier state for next graph replay ----
    __syncthreads();
    if (t == 0) {
        unsigned v = atomicAdd(&g_done, 1u);
        if (v == (unsigned)(GRID_ - 1)) {
            atomicExch(&g_bar, 0u);
            atomicExch(&g_done, 0u);
        }
    }
}

// ---------------------------------------------------------------------------
// Launch. Inputs (metadata order):
//   0: q_alpha [B,W,R]  1: k [B,W,R]  2: h_norm [B,W,D]
//   3: gamma_vec [R]    4: causal_mask (unused)  5: decay_diff (unused)
// out: float32 [B,W,D]
// ---------------------------------------------------------------------------
extern "C" void kernel_launch(void* const* d_in, const int* in_sizes, int n_in,
                              void* d_out, int out_size)
{
    const float* q     = (const float*)d_in[0];
    const float* k     = (const float*)d_in[1];
    const float* h     = (const float*)d_in[2];
    const float* gamma = (const float*)d_in[3];
    float* out         = (float*)d_out;

    k_fused<<<GRID_, 512>>>(q, k, h, gamma, out);
}